// round 16
// baseline (speedup 1.0000x reference)
#include <cuda_runtime.h>
#include <cuda_bf16.h>
#include <cstdint>

// ---------------------------------------------------------------------------
// MemristiveLinear == y = x @ w + b (512^3 fp32), tcgen05 bf16 split:
//   x = xh+xl, w = wh+wl;  y ~= xh@wh + xh@wl + xl@wh  (+b)
//
// R16: NO split-K, NO join. 64 CTAs (one per 128x32 output tile), full
//   K=512 per CTA in 4 phases of 128-k over a 2-stage smem ring (R9's
//   validated 80KB stage layout + descriptor offsets). Each phase is the
//   R13-R15 validated convert/MMA overlap engine:
//     (p>=2: all-thread fast-path mbar wait on the stage's MMA-complete)
//     -> STS from prefetched regs -> prefetch next phase LDGs -> sync
//     -> tid0: proxy fence + 24 MMA dispatches + commit.
//   Epilogue: warps 0-3 wait the final commit, 2x LDTM x16 (single wait),
//   add bias, write Y DIRECTLY; warp 4 deallocs TMEM in parallel.
// All tcgen05 constants (idesc, swizzle, blocked-atom offsets) validated
// R5-R15. Generic compute_103 pass gets a correct fallback (never runs).
// ---------------------------------------------------------------------------

#if defined(__CUDA_ARCH_FEAT_SM103_ALL) || defined(__CUDA_ARCH_FEAT_SM100_ALL) || \
    defined(__CUDA_ARCH_FEAT_SM101_ALL) || defined(__CUDA_ARCH_SPECIFIC__) ||     \
    defined(__CUDA_ARCH_FAMILY_SPECIFIC__)
#define TC_OK 1
#else
#define TC_OK 0
#endif

#define MD 512
#define ND 512
#define KD 512
#define NT 1024

#define SWZ(o) ((o) ^ (((o) >> 3) & 0x70))
#define DESC_BASE 0x4000404000010000ull
#define MK_DESC(addr) (DESC_BASE | (((unsigned long long)((addr) >> 4)) & 0x3FFF))
// kind::f16 idesc: F32 acc, BF16 a/b, M=128, N=32 (validated R5-R15)
#define IDESC ((1u << 4) | (1u << 7) | (1u << 10) | (4u << 17) | (8u << 24))

// smem map (relative to 1024-aligned base):
//   0: tmem ptr | 8,16: mbar[2] | 128: bias[32]
//   stage s at 1024 + s*81920: Ah 32K | Al 32K | Wh 8K | Wl 8K
#define STAGE0 1024
#define STAGE_STRIDE 81920
#define ST_AL 32768
#define ST_WH 65536
#define ST_WL 73728
#define SMEM_DYN (STAGE0 + 2 * STAGE_STRIDE + 1024)  // 166912

__device__ __forceinline__ uint32_t s2u(const void* p) {
    uint32_t a;
    asm("{ .reg .u64 t; cvta.to.shared.u64 t, %1; cvt.u32.u64 %0, t; }"
        : "=r"(a) : "l"(p));
    return a;
}

// Split two fp32 into packed bf16x2 hi + lo (a in low half). Validated R6-R15.
__device__ __forceinline__ void split2(float a, float b, unsigned& h,
                                       unsigned& l) {
    unsigned hp;
    asm("cvt.rn.bf16x2.f32 %0, %1, %2;" : "=r"(hp) : "f"(b), "f"(a));
    float fa = __uint_as_float(hp << 16);
    float fb = __uint_as_float(hp & 0xffff0000u);
    float ra = a - fa;
    float rb = b - fb;
    asm("cvt.rn.bf16x2.f32 %0, %1, %2;" : "=r"(l) : "f"(rb), "f"(ra));
    h = hp;
}

#if TC_OK
__device__ __forceinline__ void mma_f16_ss(uint32_t d, unsigned long long ad,
                                           unsigned long long bd,
                                           uint32_t idesc, uint32_t en) {
    asm volatile(
        "{\n\t.reg .pred p;\n\tsetp.ne.u32 p, %5, 0;\n\t"
        "tcgen05.mma.cta_group::1.kind::f16 [%0], %1, %2, %3, {%4, %4, %4, %4}, p;\n\t}"
        :: "r"(d), "l"(ad), "l"(bd), "r"(idesc), "r"(0u), "r"(en)
        : "memory");
}

#define MBAR_INIT(a) \
    asm volatile("mbarrier.init.shared.b64 [%0], %1;" :: "r"(a), "r"(1u) : "memory")

#define MBAR_WAITP(a, ph) do {                                                \
    unsigned _m = (a), _p = (ph), _d;                                         \
    asm volatile("{\n\t.reg .pred p;\n\t"                                     \
        "mbarrier.try_wait.parity.acquire.cta.shared::cta.b64 p, [%1], %2;\n\t" \
        "selp.b32 %0, 1, 0, p;\n\t}" : "=r"(_d) : "r"(_m), "r"(_p) : "memory"); \
    if (!_d) {                                                                \
        asm volatile("{\n\t.reg .pred P1;\n\t"                                \
            "WL_%=:\n\t"                                                      \
            "mbarrier.try_wait.parity.acquire.cta.shared::cta.b64 P1, [%0], %1, 0x989680;\n\t" \
            "@P1 bra.uni WD_%=;\n\t"                                          \
            "bra.uni WL_%=;\n\t"                                              \
            "WD_%=:\n\t}" :: "r"(_m), "r"(_p) : "memory");                    \
    }                                                                         \
} while (0)

#define TC_COMMIT(a) \
    asm volatile("tcgen05.commit.cta_group::1.mbarrier::arrive::one.shared::cluster.b64 [%0];" \
                 :: "r"(a) : "memory")

#define LDTM_X16(r, addr)                                                     \
    asm volatile("tcgen05.ld.sync.aligned.32x32b.x16.b32 "                    \
        "{%0, %1, %2, %3, %4, %5, %6, %7, "                                   \
        " %8, %9, %10, %11, %12, %13, %14, %15}, [%16];"                      \
        : "=r"((r)[0]),  "=r"((r)[1]),  "=r"((r)[2]),  "=r"((r)[3]),          \
          "=r"((r)[4]),  "=r"((r)[5]),  "=r"((r)[6]),  "=r"((r)[7]),          \
          "=r"((r)[8]),  "=r"((r)[9]),  "=r"((r)[10]), "=r"((r)[11]),         \
          "=r"((r)[12]), "=r"((r)[13]), "=r"((r)[14]), "=r"((r)[15])          \
        : "r"(addr))
#endif  // TC_OK

__global__ __launch_bounds__(NT, 1)
void fused_kernel(const float* __restrict__ X, const float* __restrict__ W,
                  const float* __restrict__ Bias, float* __restrict__ Y) {
    extern __shared__ char dsm[];
    const int tid = threadIdx.x;
    const int n0 = blockIdx.x * 32;
    const int m0 = blockIdx.y * 128;

#if TC_OK
    const uint32_t raw = s2u(dsm);
    const uint32_t base = (raw + 1023u) & ~1023u;
    char* dbase = dsm + (base - raw);

    const int wid = tid >> 5;
    const int lid = tid & 31;

    // ---- convert geometry (per 128-k phase; validated R13-R15) -----------
    const int arow0 = tid >> 5;            // + 32*j
    const int kq = tid & 31;               // float4 idx within 128-k phase
    const int aicb = ((4 * kq) & 63) * 2;  // byte off within atom row
    const int aac = kq >> 4;               // atom col within stage (0/1)
    const float* xb = X + 4 * kq;
    const int wn = tid & 31;               // lane = n column (coalesced)
    const int wp = tid >> 5;               // k-pair selector (0..31)
    const float* wb = W + n0 + wn;
    const int nbase = (wn >> 3) * 1024 + (wn & 7) * 128;
    // A smem offset (same for every phase; stage base differs)
    int aoff[4];
#pragma unroll
    for (int j = 0; j < 4; j++) {
        const int row = j * 32 + arow0;
        aoff[j] = SWZ(((row >> 3) + aac * 16) * 1024 + (row & 7) * 128 + aicb);
    }
    const int woff0 = SWZ(nbase + ((2 * wp) & 63) * 2);          // kg<64
    const int woff1 = SWZ(nbase + 4096 + ((2 * wp) & 63) * 2);   // kg>=64

    // ---- issue phase-0 LDGs first (overlap alloc/init latency) ----------
    float4 xr[4];
    float wv[4];
#pragma unroll
    for (int j = 0; j < 4; j++)
        xr[j] = *(const float4*)(xb + (size_t)(m0 + j * 32 + arow0) * KD);
    wv[0] = wb[(size_t)(2 * wp) * ND];
    wv[1] = wb[(size_t)(2 * wp + 1) * ND];
    wv[2] = wb[(size_t)(64 + 2 * wp) * ND];
    wv[3] = wb[(size_t)(64 + 2 * wp + 1) * ND];

    // Prefetch bias into smem.
    if (tid < 8)
        *(float4*)(dbase + 128 + 16 * tid) = ((const float4*)(Bias + n0))[tid];

    if (wid == 0)
        asm volatile(
            "tcgen05.alloc.cta_group::1.sync.aligned.shared::cta.b32 [%0], %1;"
            :: "r"(base), "r"(32u) : "memory");
    if (tid == 0) {
        MBAR_INIT(base + 8);
        MBAR_INIT(base + 16);
    }

    uint32_t tmem = 0;

#pragma unroll
    for (int p = 0; p < 4; p++) {
        const int s = p & 1;
        char* stp = dbase + STAGE0 + s * STAGE_STRIDE;
        const uint32_t stb = base + STAGE0 + s * STAGE_STRIDE;

        // Stage reuse guard: MMA(p-2) complete (finished during phase p-1's
        // convert -> fast-path wait).
        if (p >= 2) MBAR_WAITP(base + 8 + 8 * s, 0);

        // ---- STS phase p (from regs loaded last iteration) ---------------
#pragma unroll
        for (int j = 0; j < 4; j++) {
            unsigned h01, l01, h23, l23;
            split2(xr[j].x, xr[j].y, h01, l01);
            split2(xr[j].z, xr[j].w, h23, l23);
            *(uint2*)(stp + aoff[j]) = make_uint2(h01, h23);
            *(uint2*)(stp + ST_AL + aoff[j]) = make_uint2(l01, l23);
        }
        {
            unsigned h, l;
            split2(wv[0], wv[1], h, l);
            *(unsigned*)(stp + ST_WH + woff0) = h;
            *(unsigned*)(stp + ST_WL + woff0) = l;
            split2(wv[2], wv[3], h, l);
            *(unsigned*)(stp + ST_WH + woff1) = h;
            *(unsigned*)(stp + ST_WL + woff1) = l;
        }

        // ---- prefetch phase p+1 (overlaps barrier + MMA dispatch) --------
        if (p < 3) {
            const int kb = (p + 1) * 128;
#pragma unroll
            for (int j = 0; j < 4; j++)
                xr[j] = *(const float4*)(xb + kb +
                                         (size_t)(m0 + j * 32 + arow0) * KD);
            wv[0] = wb[(size_t)(kb + 2 * wp) * ND];
            wv[1] = wb[(size_t)(kb + 2 * wp + 1) * ND];
            wv[2] = wb[(size_t)(kb + 64 + 2 * wp) * ND];
            wv[3] = wb[(size_t)(kb + 64 + 2 * wp + 1) * ND];
        }

        __syncthreads();                  // BAR drains this phase's STS
        if (p == 0)
            asm("ld.shared.b32 %0, [%1];" : "=r"(tmem) : "r"(base));

        if (tid == 0) {
            asm volatile("fence.proxy.async.shared::cta;" ::: "memory");
            const unsigned long long ah = MK_DESC(stb);
            const unsigned long long al = MK_DESC(stb + ST_AL);
            const unsigned long long bh = MK_DESC(stb + ST_WH);
            const unsigned long long bl = MK_DESC(stb + ST_WL);
#pragma unroll
            for (int ks = 0; ks < 8; ks++) {
                const int ao = 2 * (ks & 3) + 1024 * (ks >> 2);
                const int bo = 2 * (ks & 3) + 256 * (ks >> 2);
                mma_f16_ss(tmem, ah + ao, bh + bo, IDESC,
                           (p == 0 && ks == 0) ? 0u : 1u);
                mma_f16_ss(tmem, ah + ao, bl + bo, IDESC, 1u);
                mma_f16_ss(tmem, al + ao, bh + bo, IDESC, 1u);
            }
            TC_COMMIT(base + 8 + 8 * s);
        }
    }

    // ---- epilogue: direct Y write (no join, no partials) -----------------
    uint32_t d0[16], d1[16];
    if (wid < 4) {
        // mbar[1]: commits at p=1 (parity 0->1) and p=3 (1->2). Waiting
        // parity 1 = after the p=3 commit; MMAs complete in order.
        MBAR_WAITP(base + 16, 1);
        asm volatile("tcgen05.fence::after_thread_sync;" ::: "memory");
        LDTM_X16(d0, tmem);
        LDTM_X16(d1, tmem + 16);
        asm volatile("tcgen05.wait::ld.sync.aligned;" ::: "memory");
    }
    __syncthreads();                      // TMEM reads done CTA-wide
    if (wid == 4) {
        asm volatile("tcgen05.relinquish_alloc_permit.cta_group::1.sync.aligned;");
        asm volatile("tcgen05.dealloc.cta_group::1.sync.aligned.b32 %0, %1;"
                     :: "r"(tmem), "r"(32u));
    }
    if (wid < 4) {
        float* yr = Y + (size_t)(m0 + wid * 32 + lid) * ND + n0;
        const float4* bias4 = (const float4*)(dbase + 128);
#pragma unroll
        for (int g = 0; g < 4; g++) {
            float4 bb = bias4[g];
            float4 r;
            r.x = __uint_as_float(d0[4 * g + 0]) + bb.x;
            r.y = __uint_as_float(d0[4 * g + 1]) + bb.y;
            r.z = __uint_as_float(d0[4 * g + 2]) + bb.z;
            r.w = __uint_as_float(d0[4 * g + 3]) + bb.w;
            *(float4*)(yr + 4 * g) = r;
            float4 bb2 = bias4[4 + g];
            float4 r2;
            r2.x = __uint_as_float(d1[4 * g + 0]) + bb2.x;
            r2.y = __uint_as_float(d1[4 * g + 1]) + bb2.y;
            r2.z = __uint_as_float(d1[4 * g + 2]) + bb2.z;
            r2.w = __uint_as_float(d1[4 * g + 3]) + bb2.w;
            *(float4*)(yr + 16 + 4 * g) = r2;
        }
    }
    // no trailing sync: each warp exits when its own tail is done
#else
    // ---- generic-target fallback (compiles everywhere; never runs) -------
    const int r = tid >> 3;               // 0..127
    const int g = tid & 7;                // 4 n cols each
    float acc[4];
#pragma unroll
    for (int j = 0; j < 4; j++) acc[j] = 0.f;
    for (int k = 0; k < KD; k++) {
        const float a = X[(size_t)(m0 + r) * KD + k];
        const float* wr = W + (size_t)k * ND + n0 + 4 * g;
#pragma unroll
        for (int j = 0; j < 4; j++) acc[j] += a * wr[j];
    }
    const float* bb = Bias + n0 + 4 * g;
    float4 rr;
    rr.x = acc[0] + bb[0];
    rr.y = acc[1] + bb[1];
    rr.z = acc[2] + bb[2];
    rr.w = acc[3] + bb[3];
    *(float4*)(Y + (size_t)(m0 + r) * ND + n0 + 4 * g) = rr;
#endif
}

extern "C" void kernel_launch(void* const* d_in, const int* in_sizes, int n_in,
                              void* d_out, int out_size) {
    const float* x = (const float*)d_in[0];  // [512, 512]
    const float* w = (const float*)d_in[1];  // [512, 512]
    const float* b = (const float*)d_in[2];  // [512]
    float* y = (float*)d_out;                // [512, 512]

    static bool attr_done = false;
    if (!attr_done) {
        cudaFuncSetAttribute(fused_kernel,
                             cudaFuncAttributeMaxDynamicSharedMemorySize,
                             SMEM_DYN);
        attr_done = true;
    }

    dim3 grid(ND / 32, MD / 128);  // (16, 4) = 64 CTAs
    fused_kernel<<<grid, NT, SMEM_DYN>>>(x, w, b, y);
}

// round 17
// speedup vs baseline: 1.1721x; 1.1721x over previous
#include <cuda_runtime.h>
#include <cuda_bf16.h>
#include <cstdint>

// ---------------------------------------------------------------------------
// MemristiveLinear == y = x @ w + b (512^3 fp32), tcgen05 bf16 split:
//   x = xh+xl, w = wh+wl;  y ~= xh@wh + xh@wl + xl@wh  (+b)
//
// R17: revert to R15 (best: split-K x2, 1024 thr, two-phase convert/MMA
//   overlap, fence-promotion join — R16 proved phase count >> join cost)
//   plus ONE register-neutral fix:
//   - the 4 MMA descriptors were computed in ALL threads (8 wasted regs);
//     now computed only inside the tid==0 dispatch blocks
//   - the freed registers prefetch ALL FOUR phase-2 A-rows BEFORE the
//     phase-1 sync, hiding their L2/DRAM latency under the barrier +
//     phase-1 MMA dispatches (R15 could only prefetch 2 of 4)
// All tcgen05 constants and the smem layout are the R5-R15 validated ones.
// Generic compute_103 pass gets a correct fallback body (never runs).
// ---------------------------------------------------------------------------

#if defined(__CUDA_ARCH_FEAT_SM103_ALL) || defined(__CUDA_ARCH_FEAT_SM100_ALL) || \
    defined(__CUDA_ARCH_FEAT_SM101_ALL) || defined(__CUDA_ARCH_SPECIFIC__) ||     \
    defined(__CUDA_ARCH_FAMILY_SPECIFIC__)
#define TC_OK 1
#else
#define TC_OK 0
#endif

#define MD 512
#define ND 512
#define KD 512
#define KH 256                       // K per split-K half
#define NT 1024

__device__ float gPart[2][MD * ND];  // split-K partials (2 MB)
__device__ int gCnt[64];             // per-tile semaphores (zero-init)

#define SWZ(o) ((o) ^ (((o) >> 3) & 0x70))
#define DESC_BASE 0x4000404000010000ull
#define MK_DESC(addr) (DESC_BASE | (((unsigned long long)((addr) >> 4)) & 0x3FFF))
// kind::f16 idesc: F32 acc, BF16 a/b, M=128, N=32 (validated R5-R16)
#define IDESC ((1u << 4) | (1u << 7) | (1u << 10) | (4u << 17) | (8u << 24))

// smem map (relative to 1024-aligned base):
//   0: tmem ptr | 8: mbar | 64: win flag | 128: bias[32]
//   Ah @ 1024 (64K) | Al @ 66560 (64K) | Wh @ 132096 (16K) | Wl @ 148480 (16K)
#define OFF_AH 1024
#define OFF_AL 66560
#define OFF_WH 132096
#define OFF_WL 148480
#define SMEM_DYN 166912

__device__ __forceinline__ uint32_t s2u(const void* p) {
    uint32_t a;
    asm("{ .reg .u64 t; cvta.to.shared.u64 t, %1; cvt.u32.u64 %0, t; }"
        : "=r"(a) : "l"(p));
    return a;
}

// Split two fp32 into packed bf16x2 hi + lo (a in low half). Validated R6-R16.
__device__ __forceinline__ void split2(float a, float b, unsigned& h,
                                       unsigned& l) {
    unsigned hp;
    asm("cvt.rn.bf16x2.f32 %0, %1, %2;" : "=r"(hp) : "f"(b), "f"(a));
    float fa = __uint_as_float(hp << 16);
    float fb = __uint_as_float(hp & 0xffff0000u);
    float ra = a - fa;
    float rb = b - fb;
    asm("cvt.rn.bf16x2.f32 %0, %1, %2;" : "=r"(l) : "f"(rb), "f"(ra));
    h = hp;
}

#if TC_OK
__device__ __forceinline__ void mma_f16_ss(uint32_t d, unsigned long long ad,
                                           unsigned long long bd,
                                           uint32_t idesc, uint32_t en) {
    asm volatile(
        "{\n\t.reg .pred p;\n\tsetp.ne.u32 p, %5, 0;\n\t"
        "tcgen05.mma.cta_group::1.kind::f16 [%0], %1, %2, %3, {%4, %4, %4, %4}, p;\n\t}"
        :: "r"(d), "l"(ad), "l"(bd), "r"(idesc), "r"(0u), "r"(en)
        : "memory");
}

#define MBAR_INIT(a) \
    asm volatile("mbarrier.init.shared.b64 [%0], %1;" :: "r"(a), "r"(1u) : "memory")

#define MBAR_WAITP(a, ph) do {                                                \
    unsigned _m = (a), _p = (ph), _d;                                         \
    asm volatile("{\n\t.reg .pred p;\n\t"                                     \
        "mbarrier.try_wait.parity.acquire.cta.shared::cta.b64 p, [%1], %2;\n\t" \
        "selp.b32 %0, 1, 0, p;\n\t}" : "=r"(_d) : "r"(_m), "r"(_p) : "memory"); \
    if (!_d) {                                                                \
        asm volatile("{\n\t.reg .pred P1;\n\t"                                \
            "WL_%=:\n\t"                                                      \
            "mbarrier.try_wait.parity.acquire.cta.shared::cta.b64 P1, [%0], %1, 0x989680;\n\t" \
            "@P1 bra.uni WD_%=;\n\t"                                          \
            "bra.uni WL_%=;\n\t"                                              \
            "WD_%=:\n\t}" :: "r"(_m), "r"(_p) : "memory");                    \
    }                                                                         \
} while (0)

#define TC_COMMIT(a) \
    asm volatile("tcgen05.commit.cta_group::1.mbarrier::arrive::one.shared::cluster.b64 [%0];" \
                 :: "r"(a) : "memory")

#define LDTM_X16(r, addr)                                                     \
    asm volatile("tcgen05.ld.sync.aligned.32x32b.x16.b32 "                    \
        "{%0, %1, %2, %3, %4, %5, %6, %7, "                                   \
        " %8, %9, %10, %11, %12, %13, %14, %15}, [%16];"                      \
        : "=r"((r)[0]),  "=r"((r)[1]),  "=r"((r)[2]),  "=r"((r)[3]),          \
          "=r"((r)[4]),  "=r"((r)[5]),  "=r"((r)[6]),  "=r"((r)[7]),          \
          "=r"((r)[8]),  "=r"((r)[9]),  "=r"((r)[10]), "=r"((r)[11]),         \
          "=r"((r)[12]), "=r"((r)[13]), "=r"((r)[14]), "=r"((r)[15])          \
        : "r"(addr))
#endif  // TC_OK

__global__ __launch_bounds__(NT, 1)
void fused_kernel(const float* __restrict__ X, const float* __restrict__ W,
                  const float* __restrict__ Bias, float* __restrict__ Y) {
    extern __shared__ char dsm[];
    const int tid = threadIdx.x;
    const int n0 = blockIdx.x * 32;
    const int m0 = blockIdx.y * 128;
    const int kz = blockIdx.z;            // split-K half 0/1
    const int tile = blockIdx.y * 16 + blockIdx.x;

#if TC_OK
    const uint32_t raw = s2u(dsm);
    const uint32_t base = (raw + 1023u) & ~1023u;
    char* dbase = dsm + (base - raw);

    const int wid = tid >> 5;
    const int lid = tid & 31;

    // ---- convert geometry (validated R13-R15) ----------------------------
    const int arow0 = tid >> 5;            // + 32*j
    const int kq = tid & 31;               // float4 idx within 128-k half
    const int aicb = ((4 * kq) & 63) * 2;  // byte off within atom row
    const float* xb = X + kz * KH + 4 * kq;
    const int wn = tid & 31;               // lane = n column (coalesced)
    const int wp = tid >> 5;               // k-pair selector (0..31)
    const float* wb = W + (size_t)(kz * KH) * ND + n0 + wn;
    const int nbase = (wn >> 3) * 1024 + (wn & 7) * 128;

    // ---- issue ALL phase-1 LDGs first (overlap alloc/init latency) ------
    float4 xr[4];
#pragma unroll
    for (int j = 0; j < 4; j++)
        xr[j] = *(const float4*)(xb + (size_t)(m0 + j * 32 + arow0) * KD);
    float w0a = wb[(size_t)(2 * wp) * ND];
    float w1a = wb[(size_t)(2 * wp + 1) * ND];
    float w0b = wb[(size_t)(64 + 2 * wp) * ND];
    float w1b = wb[(size_t)(64 + 2 * wp + 1) * ND];

    // Prefetch bias into smem.
    if (tid < 8)
        *(float4*)(dbase + 128 + 16 * tid) = ((const float4*)(Bias + n0))[tid];

    if (wid == 0)
        asm volatile(
            "tcgen05.alloc.cta_group::1.sync.aligned.shared::cta.b32 [%0], %1;"
            :: "r"(base), "r"(32u) : "memory");
    if (tid == 0) MBAR_INIT(base + 8);

    // ---- phase 1: convert k in [0,128) (data already in flight) ----------
    {
#pragma unroll
        for (int j = 0; j < 4; j++) {
            const int row = j * 32 + arow0;
            unsigned h01, l01, h23, l23;
            split2(xr[j].x, xr[j].y, h01, l01);
            split2(xr[j].z, xr[j].w, h23, l23);
            const int ac = kq >> 4;        // ph=0 atom col
            const int off = SWZ(((row >> 3) + ac * 16) * 1024 +
                                (row & 7) * 128 + aicb);
            *(uint2*)(dbase + OFF_AH + off) = make_uint2(h01, h23);
            *(uint2*)(dbase + OFF_AL + off) = make_uint2(l01, l23);
        }
        {
            unsigned h, l;
            const int kg = 2 * wp;
            split2(w0a, w1a, h, l);
            const int off = SWZ(nbase + (kg >> 6) * 4096 + (kg & 63) * 2);
            *(unsigned*)(dbase + OFF_WH + off) = h;
            *(unsigned*)(dbase + OFF_WL + off) = l;
        }
        {
            unsigned h, l;
            const int kg = 64 + 2 * wp;
            split2(w0b, w1b, h, l);
            const int off = SWZ(nbase + (kg >> 6) * 4096 + (kg & 63) * 2);
            *(unsigned*)(dbase + OFF_WH + off) = h;
            *(unsigned*)(dbase + OFF_WL + off) = l;
        }
    }

    // ---- phase-2 register prefetch: ALL FOUR A rows + all W pairs BEFORE
    //      the sync (regs freed by moving descriptor math into tid0) -------
    float4 xr2[4];
#pragma unroll
    for (int j = 0; j < 4; j++)
        xr2[j] =
            *(const float4*)(xb + 128 + (size_t)(m0 + j * 32 + arow0) * KD);
    float pw0a = wb[(size_t)(128 + 2 * wp) * ND];
    float pw1a = wb[(size_t)(128 + 2 * wp + 1) * ND];
    float pw0b = wb[(size_t)(192 + 2 * wp) * ND];
    float pw1b = wb[(size_t)(192 + 2 * wp + 1) * ND];

    __syncthreads();                      // BAR drains phase-1 STS
    uint32_t tmem;
    asm("ld.shared.b32 %0, [%1];" : "=r"(tmem) : "r"(base));

    if (tid == 0) {
        asm volatile("fence.proxy.async.shared::cta;" ::: "memory");
        const unsigned long long ah = MK_DESC(base + OFF_AH);
        const unsigned long long al = MK_DESC(base + OFF_AL);
        const unsigned long long bh = MK_DESC(base + OFF_WH);
        const unsigned long long bl = MK_DESC(base + OFF_WL);
#pragma unroll
        for (int ks = 0; ks < 8; ks++) {
            const int ao = 2 * (ks & 3) + 1024 * (ks >> 2);
            const int bo = 2 * (ks & 3) + 256 * (ks >> 2);
            mma_f16_ss(tmem, ah + ao, bh + bo, IDESC, ks ? 1u : 0u);
            mma_f16_ss(tmem, ah + ao, bl + bo, IDESC, 1u);
            mma_f16_ss(tmem, al + ao, bh + bo, IDESC, 1u);
        }
    }

    // ---- phase 2: convert k in [128,256) (everything prefetched) ---------
    {
#pragma unroll
        for (int j = 0; j < 4; j++) {
            const float4 v = xr2[j];
            const int row = j * 32 + arow0;
            unsigned h01, l01, h23, l23;
            split2(v.x, v.y, h01, l01);
            split2(v.z, v.w, h23, l23);
            const int ac = 2 + (kq >> 4);  // ph=1 atom col
            const int off = SWZ(((row >> 3) + ac * 16) * 1024 +
                                (row & 7) * 128 + aicb);
            *(uint2*)(dbase + OFF_AH + off) = make_uint2(h01, h23);
            *(uint2*)(dbase + OFF_AL + off) = make_uint2(l01, l23);
        }
        {
            unsigned h, l;
            const int kg = 128 + 2 * wp;
            split2(pw0a, pw1a, h, l);
            const int off = SWZ(nbase + (kg >> 6) * 4096 + (kg & 63) * 2);
            *(unsigned*)(dbase + OFF_WH + off) = h;
            *(unsigned*)(dbase + OFF_WL + off) = l;
        }
        {
            unsigned h, l;
            const int kg = 192 + 2 * wp;
            split2(pw0b, pw1b, h, l);
            const int off = SWZ(nbase + (kg >> 6) * 4096 + (kg & 63) * 2);
            *(unsigned*)(dbase + OFF_WH + off) = h;
            *(unsigned*)(dbase + OFF_WL + off) = l;
        }
    }
    __syncthreads();

    if (tid == 0) {
        asm volatile("fence.proxy.async.shared::cta;" ::: "memory");
        const unsigned long long ah = MK_DESC(base + OFF_AH);
        const unsigned long long al = MK_DESC(base + OFF_AL);
        const unsigned long long bh = MK_DESC(base + OFF_WH);
        const unsigned long long bl = MK_DESC(base + OFF_WL);
#pragma unroll
        for (int ks = 8; ks < 16; ks++) {
            const int ao = 2 * (ks & 3) + 1024 * (ks >> 2);
            const int bo = 2 * (ks & 3) + 256 * (ks >> 2);
            mma_f16_ss(tmem, ah + ao, bh + bo, IDESC, 1u);
            mma_f16_ss(tmem, ah + ao, bl + bo, IDESC, 1u);
            mma_f16_ss(tmem, al + ao, bh + bo, IDESC, 1u);
        }
        TC_COMMIT(base + 8);
    }

    // ---- warps 0-3 wait MMA completion DIRECTLY; publish partial ---------
    if (wid < 4) {
        MBAR_WAITP(base + 8, 0);
        asm volatile("tcgen05.fence::after_thread_sync;" ::: "memory");

        uint32_t d0[16], d1[16];
        LDTM_X16(d0, tmem);
        LDTM_X16(d1, tmem + 16);
        asm volatile("tcgen05.wait::ld.sync.aligned;" ::: "memory");

        float* pp = &gPart[kz][(size_t)(m0 + wid * 32 + lid) * ND + n0];
#pragma unroll
        for (int g = 0; g < 4; g++) {
            float4 r;
            r.x = __uint_as_float(d0[4 * g + 0]);
            r.y = __uint_as_float(d0[4 * g + 1]);
            r.z = __uint_as_float(d0[4 * g + 2]);
            r.w = __uint_as_float(d0[4 * g + 3]);
            *(float4*)(pp + 4 * g) = r;
            float4 r2;
            r2.x = __uint_as_float(d1[4 * g + 0]);
            r2.y = __uint_as_float(d1[4 * g + 1]);
            r2.z = __uint_as_float(d1[4 * g + 2]);
            r2.w = __uint_as_float(d1[4 * g + 3]);
            *(float4*)(pp + 16 + 4 * g) = r2;
        }
    }

    // ---- join: warp1 deallocs TMEM in PARALLEL with tid0's atomic --------
    __syncthreads();                      // STGs + all TMEM reads complete
    if (wid == 1) {
        asm volatile("tcgen05.relinquish_alloc_permit.cta_group::1.sync.aligned;");
        asm volatile("tcgen05.dealloc.cta_group::1.sync.aligned.b32 %0, %1;"
                     :: "r"(tmem), "r"(32u));
    }
    if (tid == 0) {
        asm volatile("fence.acq_rel.gpu;" ::: "memory");
        const int old = atomicAdd(&gCnt[tile], 1);
        asm volatile("fence.acq_rel.gpu;" ::: "memory");
        *(int*)(dbase + 64) = (old == 1);
    }
    __syncthreads();

    if (*(int*)(dbase + 64)) {
        // Winner: one float4 of output per thread (1024 x 4 = 4096 = tile).
        const int row = tid >> 3, q = tid & 7;
        const size_t idx = (size_t)(m0 + row) * ND + n0 + 4 * q;
        float4 p0 = *(const float4*)&gPart[0][idx];
        float4 p1 = *(const float4*)&gPart[1][idx];
        float4 bb = *(const float4*)(dbase + 128 + 16 * q);
        float4 r;
        r.x = p0.x + p1.x + bb.x;
        r.y = p0.y + p1.y + bb.y;
        r.z = p0.z + p1.z + bb.z;
        r.w = p0.w + p1.w + bb.w;
        *(float4*)(Y + idx) = r;
        if (tid == 0) gCnt[tile] = 0;     // reset for next graph replay
    }
    // no trailing sync: each warp exits when its own tail is done
#else
    // ---- generic-target fallback (compiles everywhere; never runs) -------
    __shared__ int sflag;
    const int r = tid >> 3;               // 0..127
    const int g = tid & 7;                // 4 n cols each
    float acc[4];
#pragma unroll
    for (int j = 0; j < 4; j++) acc[j] = 0.f;
    for (int k = kz * KH; k < kz * KH + KH; k++) {
        const float a = X[(size_t)(m0 + r) * KD + k];
        const float* wr = W + (size_t)k * ND + n0 + 4 * g;
#pragma unroll
        for (int j = 0; j < 4; j++) acc[j] += a * wr[j];
    }
    {
        float* pp = &gPart[kz][(size_t)(m0 + r) * ND + n0 + 4 * g];
#pragma unroll
        for (int j = 0; j < 4; j++) pp[j] = acc[j];
    }
    __threadfence();
    __syncthreads();
    if (tid == 0) sflag = (atomicAdd(&gCnt[tile], 1) == 1);
    __syncthreads();
    if (sflag) {
        __threadfence();
        const size_t idx = (size_t)(m0 + r) * ND + n0 + 4 * g;
        float4 p0 = *(const float4*)&gPart[0][idx];
        float4 p1 = *(const float4*)&gPart[1][idx];
        const float* bb = Bias + n0 + 4 * g;
        float4 rr;
        rr.x = p0.x + p1.x + bb[0];
        rr.y = p0.y + p1.y + bb[1];
        rr.z = p0.z + p1.z + bb[2];
        rr.w = p0.w + p1.w + bb[3];
        *(float4*)(Y + idx) = rr;
        if (tid == 0) gCnt[tile] = 0;
    }
#endif
}

extern "C" void kernel_launch(void* const* d_in, const int* in_sizes, int n_in,
                              void* d_out, int out_size) {
    const float* x = (const float*)d_in[0];  // [512, 512]
    const float* w = (const float*)d_in[1];  // [512, 512]
    const float* b = (const float*)d_in[2];  // [512]
    float* y = (float*)d_out;                // [512, 512]

    static bool attr_done = false;
    if (!attr_done) {
        cudaFuncSetAttribute(fused_kernel,
                             cudaFuncAttributeMaxDynamicSharedMemorySize,
                             SMEM_DYN);
        attr_done = true;
    }

    dim3 grid(ND / 32, MD / 128, 2);  // (16, 4, 2) = 128 CTAs, one wave
    fused_kernel<<<grid, NT, SMEM_DYN>>>(x, w, b, y);
}